// round 4
// baseline (speedup 1.0000x reference)
#include <cuda_runtime.h>
#include <cuda_bf16.h>

// Problem constants (fixed by dataset): N=2,000,000 rows, P=64 features, C=100 classes.
#define PFEAT      64
#define NCLASS     100
#define NWARPS     8          // warps per CTA; class ownership = cls & 7
#define THREADS1   (NWARPS * 32)
#define GRID1      592        // 148 SMs * 4 resident CTAs
#define BINS4      (NCLASS * 32)                    // float4 bins: [class][lanepair]
#define SMEM1      (BINS4 * 16 + NCLASS * 4)        // 51,600 B -> dynamic smem (opt-in)

// Deterministic scratch (written, then reduced in fixed order; no float atomics anywhere).
__device__ float4 g_part[(size_t)GRID1 * BINS4];    // ~30.3 MB
__device__ float  g_cnt[GRID1 * NCLASS];
__device__ double g_class[NCLASS];

// ---------------------------------------------------------------------------
// Kernel 1: per-CTA accumulation of s, ss (per class/feature) and counts.
// Warp w exclusively owns classes with (cls & 7) == w  ->  no atomics.
// Up to 4 owned rows are batched per loop trip so the 256B row loads issue
// back-to-back (MLP~4 per warp) instead of serially.
// ---------------------------------------------------------------------------
__global__ __launch_bounds__(THREADS1)
void k1_accumulate(const float2* __restrict__ x2,
                   const int* __restrict__ t, int N)   // t is int32 (JAX x64 disabled)
{
    extern __shared__ unsigned char smem_raw[];
    float4* acc = reinterpret_cast<float4*>(smem_raw);               // BINS4 entries
    float*  cnt = reinterpret_cast<float*>(smem_raw + BINS4 * 16);   // NCLASS entries

    const int tid  = threadIdx.x;
    const int w    = tid >> 5;
    const int lane = tid & 31;

    for (int i = tid; i < BINS4; i += THREADS1) acc[i] = make_float4(0.f, 0.f, 0.f, 0.f);
    for (int i = tid; i < NCLASS; i += THREADS1) cnt[i] = 0.f;
    __syncthreads();

    const int chunk = (N + GRID1 - 1) / GRID1;
    const int beg   = blockIdx.x * chunk;
    const int end   = min(N, beg + chunk);

    for (int base = beg; base < end; base += 32) {
        int r   = base + lane;
        int cls = (r < end) ? t[r] : -1;             // int32, coalesced 128B/warp, L1-hot
        // Defensive bound: guarantees all smem indices in range even on bad data.
        bool own = (cls >= 0) && (cls < NCLASS) && ((cls & (NWARPS - 1)) == w);
        unsigned m = __ballot_sync(0xffffffffu, own);

        while (m) {
            // Extract up to 4 owned-row slots first (uniform), THEN issue loads.
            int b0 = __ffs(m) - 1;  m &= m - 1;
            int b1 = -1, b2 = -1, b3 = -1;
            if (m) { b1 = __ffs(m) - 1; m &= m - 1; }
            if (m) { b2 = __ffs(m) - 1; m &= m - 1; }
            if (m) { b3 = __ffs(m) - 1; m &= m - 1; }

            int c0 = __shfl_sync(0xffffffffu, cls, b0 & 31);
            int c1 = __shfl_sync(0xffffffffu, cls, b1 & 31);
            int c2 = __shfl_sync(0xffffffffu, cls, b2 & 31);
            int c3 = __shfl_sync(0xffffffffu, cls, b3 & 31);

            // 4 independent 256B coalesced row loads (lane -> features 2*lane, 2*lane+1)
            float2 v0, v1, v2, v3;
            v0 = x2[(size_t)(base + b0) * (PFEAT / 2) + lane];
            if (b1 >= 0) v1 = x2[(size_t)(base + b1) * (PFEAT / 2) + lane];
            if (b2 >= 0) v2 = x2[(size_t)(base + b2) * (PFEAT / 2) + lane];
            if (b3 >= 0) v3 = x2[(size_t)(base + b3) * (PFEAT / 2) + lane];

            {   // row b0 (always valid)
                int idx = c0 * 32 + lane;            // 16B-stride: conflict-free
                float4 a = acc[idx];
                a.x += v0.x; a.y += v0.y; a.z += v0.x * v0.x; a.w += v0.y * v0.y;
                acc[idx] = a;
                if (lane == 0) cnt[c0] += 1.0f;      // exclusive to warp w -> plain RMW
            }
            if (b1 >= 0) {
                int idx = c1 * 32 + lane;
                float4 a = acc[idx];
                a.x += v1.x; a.y += v1.y; a.z += v1.x * v1.x; a.w += v1.y * v1.y;
                acc[idx] = a;
                if (lane == 0) cnt[c1] += 1.0f;
            }
            if (b2 >= 0) {
                int idx = c2 * 32 + lane;
                float4 a = acc[idx];
                a.x += v2.x; a.y += v2.y; a.z += v2.x * v2.x; a.w += v2.y * v2.y;
                acc[idx] = a;
                if (lane == 0) cnt[c2] += 1.0f;
            }
            if (b3 >= 0) {
                int idx = c3 * 32 + lane;
                float4 a = acc[idx];
                a.x += v3.x; a.y += v3.y; a.z += v3.x * v3.x; a.w += v3.y * v3.y;
                acc[idx] = a;
                if (lane == 0) cnt[c3] += 1.0f;
            }
        }
    }
    __syncthreads();

    const size_t off = (size_t)blockIdx.x * BINS4;
    for (int i = tid; i < BINS4; i += THREADS1) g_part[off + i] = acc[i];
    for (int i = tid; i < NCLASS; i += THREADS1) g_cnt[blockIdx.x * NCLASS + i] = cnt[i];
}

// ---------------------------------------------------------------------------
// Kernel 2: one CTA per class. Reduce GRID1 partials in fixed order, then
// sum over features of (ss - s^2/n)/(n-1) in double -> g_class[c].
// ---------------------------------------------------------------------------
__global__ __launch_bounds__(64)
void k2_per_class()
{
    const int c   = blockIdx.x;
    const int tid = threadIdx.x;

    __shared__ float  s_n;
    __shared__ double s_half;

    if (tid >= 32) {                                  // warp 1: counts
        float cn = 0.f;
        for (int b = tid - 32; b < GRID1; b += 32) cn += g_cnt[b * NCLASS + c];
        #pragma unroll
        for (int o = 16; o > 0; o >>= 1) cn += __shfl_down_sync(0xffffffffu, cn, o);
        if (tid == 32) s_n = cn;
    }

    float4 a = make_float4(0.f, 0.f, 0.f, 0.f);
    if (tid < 32) {                                   // warp 0: s/ss bins (512B coalesced per b)
        for (int b = 0; b < GRID1; b++) {
            float4 p = g_part[(size_t)b * BINS4 + c * 32 + tid];
            a.x += p.x; a.y += p.y; a.z += p.z; a.w += p.w;
        }
    }
    __syncthreads();

    if (tid < 32) {
        double n  = (double)s_n;
        double in = 1.0 / n;
        double id = 1.0 / (n - 1.0);
        double contrib =
            ((double)a.z - (double)a.x * (double)a.x * in) * id +
            ((double)a.w - (double)a.y * (double)a.y * in) * id;
        #pragma unroll
        for (int o = 16; o > 0; o >>= 1)
            contrib += __shfl_down_sync(0xffffffffu, contrib, o);
        if (tid == 0) s_half = contrib;
    }
    __syncthreads();
    if (tid == 0) g_class[c] = s_half;
}

// ---------------------------------------------------------------------------
// Kernel 3: final deterministic reduction of the 100 class scalars.
// ---------------------------------------------------------------------------
__global__ void k3_final(float* __restrict__ out)
{
    if (threadIdx.x == 0) {
        double total = 0.0;
        for (int c = 0; c < NCLASS; c++) total += g_class[c];
        out[0] = (float)(total / (double)NCLASS);
    }
}

extern "C" void kernel_launch(void* const* d_in, const int* in_sizes, int n_in,
                              void* d_out, int out_size)
{
    const float2* x2  = (const float2*)d_in[0];
    const int*    t   = (const int*)d_in[1];          // int32 labels
    float*        out = (float*)d_out;
    const int N = in_sizes[0] / PFEAT;

    // Opt-in to >48KB dynamic shared memory (unconditional: no static guards).
    cudaFuncSetAttribute(k1_accumulate, cudaFuncAttributeMaxDynamicSharedMemorySize, SMEM1);

    k1_accumulate<<<GRID1, THREADS1, SMEM1>>>(x2, t, N);
    k2_per_class<<<NCLASS, 64>>>();
    k3_final<<<1, 32>>>(out);
}

// round 5
// speedup vs baseline: 1.5795x; 1.5795x over previous
#include <cuda_runtime.h>
#include <cuda_bf16.h>

// Problem constants: N=2,000,000 rows, P=64 features, C=100 classes.
#define PFEAT      64
#define NCLASS     100
#define NWARPS     16         // warps per CTA; class ownership = cls & 15
#define THREADS1   (NWARPS * 32)
#define GRID1      592        // 148 SMs * 4 resident CTAs
#define BINS4      (NCLASS * 32)                    // float4 bins: [class][lanepair]
#define SMEM1      (BINS4 * 16 + NCLASS * 4)        // 51,600 B -> dynamic smem (opt-in)

// Deterministic scratch (written, then reduced in fixed order; no float atomics anywhere).
__device__ float4 g_part[(size_t)GRID1 * BINS4];    // ~30.3 MB
__device__ float  g_cnt[GRID1 * NCLASS];
__device__ double g_class[NCLASS];

// ---------------------------------------------------------------------------
// Kernel 1: per-CTA accumulation of s, ss (per class/feature) and counts.
// Warp w exclusively owns classes with (cls & 15) == w  ->  no atomics.
// 16 warps/CTA * 4 CTAs/SM = 64 warps (100% occ) to hide the smem RMW chains.
// ---------------------------------------------------------------------------
__global__ __launch_bounds__(THREADS1, 4)
void k1_accumulate(const float2* __restrict__ x2,
                   const int* __restrict__ t, int N)   // t is int32 (JAX x64 disabled)
{
    extern __shared__ unsigned char smem_raw[];
    float4* acc = reinterpret_cast<float4*>(smem_raw);               // BINS4 entries
    float*  cnt = reinterpret_cast<float*>(smem_raw + BINS4 * 16);   // NCLASS entries

    const int tid  = threadIdx.x;
    const int w    = tid >> 5;
    const int lane = tid & 31;

    for (int i = tid; i < BINS4; i += THREADS1) acc[i] = make_float4(0.f, 0.f, 0.f, 0.f);
    for (int i = tid; i < NCLASS; i += THREADS1) cnt[i] = 0.f;
    __syncthreads();

    const int chunk = (N + GRID1 - 1) / GRID1;
    const int beg   = blockIdx.x * chunk;
    const int end   = min(N, beg + chunk);

    for (int base = beg; base < end; base += 32) {
        int r   = base + lane;
        int cls = (r < end) ? t[r] : -1;             // int32, coalesced, L1-hot across warps
        bool own = (cls >= 0) && (cls < NCLASS) && ((cls & (NWARPS - 1)) == w);
        unsigned m = __ballot_sync(0xffffffffu, own);

        while (m) {
            // Extract up to 2 owned-row slots (typical count is ~2), THEN load both.
            int b0 = __ffs(m) - 1;  m &= m - 1;
            int b1 = -1;
            if (m) { b1 = __ffs(m) - 1; m &= m - 1; }

            int c0 = __shfl_sync(0xffffffffu, cls, b0 & 31);
            int c1 = __shfl_sync(0xffffffffu, cls, b1 & 31);

            float2 v0, v1;
            v0 = x2[(size_t)(base + b0) * (PFEAT / 2) + lane];   // 256B coalesced
            if (b1 >= 0) v1 = x2[(size_t)(base + b1) * (PFEAT / 2) + lane];

            {   // row b0 (always valid)
                int idx = c0 * 32 + lane;            // 16B-stride: conflict-free
                float4 a = acc[idx];
                a.x += v0.x; a.y += v0.y; a.z += v0.x * v0.x; a.w += v0.y * v0.y;
                acc[idx] = a;
                if (lane == 0) cnt[c0] += 1.0f;      // exclusive to warp w -> plain RMW
            }
            if (b1 >= 0) {
                int idx = c1 * 32 + lane;
                float4 a = acc[idx];
                a.x += v1.x; a.y += v1.y; a.z += v1.x * v1.x; a.w += v1.y * v1.y;
                acc[idx] = a;
                if (lane == 0) cnt[c1] += 1.0f;
            }
        }
    }
    __syncthreads();

    const size_t off = (size_t)blockIdx.x * BINS4;
    for (int i = tid; i < BINS4; i += THREADS1) g_part[off + i] = acc[i];
    for (int i = tid; i < NCLASS; i += THREADS1) g_cnt[blockIdx.x * NCLASS + i] = cnt[i];
}

// ---------------------------------------------------------------------------
// Kernel 2: one CTA (256 thr) per class. 8 warps split the 592 partials,
// combine in smem, then warp 0 computes sum_f (ss - s^2/n)/(n-1) in double.
// ---------------------------------------------------------------------------
__global__ __launch_bounds__(256)
void k2_per_class()
{
    const int c    = blockIdx.x;
    const int tid  = threadIdx.x;
    const int w    = tid >> 5;
    const int lane = tid & 31;

    __shared__ float4 sacc[256];      // [warp][lane]
    __shared__ float  scnt[256];

    // Bin partials: warp w takes b = w, w+8, ... (512B coalesced per (b,warp), MLP ~74)
    float4 a = make_float4(0.f, 0.f, 0.f, 0.f);
    for (int b = w; b < GRID1; b += 8) {
        float4 p = g_part[(size_t)b * BINS4 + c * 32 + lane];
        a.x += p.x; a.y += p.y; a.z += p.z; a.w += p.w;
    }
    sacc[tid] = a;

    // Count partials: 256 threads stride the 592 blocks.
    float cn = 0.f;
    for (int b = tid; b < GRID1; b += 256) cn += g_cnt[b * NCLASS + c];
    scnt[tid] = cn;
    __syncthreads();

    if (tid < 32) {
        float4 tot = sacc[lane];
        float  n   = scnt[lane];
        #pragma unroll
        for (int j = 1; j < 8; j++) {
            float4 p = sacc[j * 32 + lane];
            tot.x += p.x; tot.y += p.y; tot.z += p.z; tot.w += p.w;
            n += scnt[j * 32 + lane];
        }
        // butterfly-reduce n so every lane has the full class count
        #pragma unroll
        for (int o = 16; o > 0; o >>= 1) n += __shfl_xor_sync(0xffffffffu, n, o);

        double dn = (double)n;
        double in = 1.0 / dn;
        double id = 1.0 / (dn - 1.0);
        double contrib =
            ((double)tot.z - (double)tot.x * (double)tot.x * in) * id +
            ((double)tot.w - (double)tot.y * (double)tot.y * in) * id;
        #pragma unroll
        for (int o = 16; o > 0; o >>= 1)
            contrib += __shfl_xor_sync(0xffffffffu, contrib, o);
        if (lane == 0) g_class[c] = contrib;
    }
}

// ---------------------------------------------------------------------------
// Kernel 3: final deterministic reduction of the 100 class scalars.
// ---------------------------------------------------------------------------
__global__ void k3_final(float* __restrict__ out)
{
    if (threadIdx.x == 0) {
        double total = 0.0;
        for (int c = 0; c < NCLASS; c++) total += g_class[c];
        out[0] = (float)(total / (double)NCLASS);
    }
}

extern "C" void kernel_launch(void* const* d_in, const int* in_sizes, int n_in,
                              void* d_out, int out_size)
{
    const float2* x2  = (const float2*)d_in[0];
    const int*    t   = (const int*)d_in[1];          // int32 labels
    float*        out = (float*)d_out;
    const int N = in_sizes[0] / PFEAT;

    cudaFuncSetAttribute(k1_accumulate, cudaFuncAttributeMaxDynamicSharedMemorySize, SMEM1);

    k1_accumulate<<<GRID1, THREADS1, SMEM1>>>(x2, t, N);
    k2_per_class<<<NCLASS, 256>>>();
    k3_final<<<1, 32>>>(out);
}